// round 1
// baseline (speedup 1.0000x reference)
#include <cuda_runtime.h>

#define NTOK 4096
#define DIM 768
#define NH 12
#define HD 64
#define RANK 4

// scratch (device globals: no allocation allowed)
__device__ float g_q[NH * NTOK * HD];
__device__ float g_k[NH * NTOK * HD];
__device__ float g_v[NH * NTOK * HD];
__device__ float g_tq[NTOK * RANK];
__device__ float g_tv[NTOK * RANK];
__device__ float g_bh[NH * NTOK * 64];
__device__ float g_bw[NH * NTOK * 64];
__device__ float g_o[NTOK * DIM];

// ---------------- kernel 1: t = x @ A^T (rank-4 LoRA down-proj) ----------------
__global__ void lora_t_kernel(const float* __restrict__ x,
                              const float* __restrict__ Aq,
                              const float* __restrict__ Av) {
    int warp = (blockIdx.x * blockDim.x + threadIdx.x) >> 5;
    int lane = threadIdx.x & 31;
    if (warp >= NTOK) return;
    const float* xr = x + warp * DIM;
    float p[8] = {0.f, 0.f, 0.f, 0.f, 0.f, 0.f, 0.f, 0.f};
    for (int i = lane; i < DIM; i += 32) {
        float xv = xr[i];
#pragma unroll
        for (int r = 0; r < RANK; r++) {
            p[r]        += xv * Aq[r * DIM + i];
            p[RANK + r] += xv * Av[r * DIM + i];
        }
    }
#pragma unroll
    for (int r = 0; r < 8; r++) {
#pragma unroll
        for (int o = 16; o; o >>= 1)
            p[r] += __shfl_xor_sync(0xffffffffu, p[r], o);
    }
    if (lane == 0) {
#pragma unroll
        for (int r = 0; r < RANK; r++) {
            g_tq[warp * RANK + r] = p[r];
            g_tv[warp * RANK + r] = p[RANK + r];
        }
    }
}

// ---------------- kernel 2: qkv = x @ W_qkv^T + b + LoRA deltas ----------------
// 64x64 tile per block, BK=16, 256 threads, 4x4 register tile per thread.
__global__ __launch_bounds__(256) void qkv_kernel(
    const float* __restrict__ x, const float* __restrict__ W,
    const float* __restrict__ b, const float* __restrict__ Bq,
    const float* __restrict__ Bv) {
    __shared__ float As[16][68];  // [k][m]
    __shared__ float Bs[16][68];  // [k][n]
    int bm = blockIdx.y * 64;
    int bn = blockIdx.x * 64;
    int tid = threadIdx.x;
    int tx = tid & 15, ty = tid >> 4;
    int lm = tid >> 2, lk = (tid & 3) * 4;
    float acc[4][4] = {};
    for (int k0 = 0; k0 < DIM; k0 += 16) {
        float4 av = *(const float4*)&x[(bm + lm) * DIM + k0 + lk];
        float4 bv = *(const float4*)&W[(bn + lm) * DIM + k0 + lk];
        As[lk + 0][lm] = av.x; As[lk + 1][lm] = av.y;
        As[lk + 2][lm] = av.z; As[lk + 3][lm] = av.w;
        Bs[lk + 0][lm] = bv.x; Bs[lk + 1][lm] = bv.y;
        Bs[lk + 2][lm] = bv.z; Bs[lk + 3][lm] = bv.w;
        __syncthreads();
#pragma unroll
        for (int k = 0; k < 16; k++) {
            float4 a4 = *(const float4*)&As[k][ty * 4];
            float4 b4 = *(const float4*)&Bs[k][tx * 4];
            float a[4] = {a4.x, a4.y, a4.z, a4.w};
            float bb[4] = {b4.x, b4.y, b4.z, b4.w};
#pragma unroll
            for (int i = 0; i < 4; i++)
#pragma unroll
                for (int j = 0; j < 4; j++) acc[i][j] += a[i] * bb[j];
        }
        __syncthreads();
    }
    // epilogue: tile never crosses a q/k/v boundary or a head boundary
    int col0 = bn + tx * 4;
    int which = col0 / DIM;
    int hcol0 = col0 - which * DIM;
    int head = hcol0 >> 6;
    int c0 = hcol0 & 63;
    float* dst = (which == 0) ? g_q : (which == 1 ? g_k : g_v);
#pragma unroll
    for (int i = 0; i < 4; i++) {
        int m = bm + ty * 4 + i;
        float v[4];
#pragma unroll
        for (int j = 0; j < 4; j++) {
            float val = acc[i][j] + b[col0 + j];
            if (which == 0) {
                const float* Br = &Bq[(hcol0 + j) * RANK];
                const float* tr = &g_tq[m * RANK];
                val += 0.25f * (tr[0] * Br[0] + tr[1] * Br[1] +
                                tr[2] * Br[2] + tr[3] * Br[3]);
            } else if (which == 2) {
                const float* Br = &Bv[(hcol0 + j) * RANK];
                const float* tr = &g_tv[m * RANK];
                val += 0.25f * (tr[0] * Br[0] + tr[1] * Br[1] +
                                tr[2] * Br[2] + tr[3] * Br[3]);
            }
            v[j] = val;
        }
        float4 o4 = {v[0], v[1], v[2], v[3]};
        *(float4*)&dst[head * (NTOK * HD) + m * HD + c0] = o4;
    }
}

// ---------------- kernel 3: decomposed rel-pos biases ----------------
// bias_h[head,i,h2] = q[head,i,:] . rel_h[h1-h2+63,:]   (h1 = i/64)
// bias_w[head,i,w2] = q[head,i,:] . rel_w[w1-w2+63,:]   (w1 = i%64)
__global__ void bias_kernel(const float* __restrict__ rel_h,
                            const float* __restrict__ rel_w) {
    int i = blockIdx.x;
    int head = blockIdx.y;
    int t = threadIdx.x;  // h2 / w2 index, 0..63
    __shared__ float qrow[64];
    qrow[t] = g_q[head * (NTOK * HD) + i * HD + t];
    __syncthreads();
    int h1 = i >> 6, w1 = i & 63;
    const float4* rh = (const float4*)&rel_h[(h1 - t + 63) * HD];
    const float4* rw = (const float4*)&rel_w[(w1 - t + 63) * HD];
    float sh = 0.f, sw = 0.f;
#pragma unroll
    for (int c4 = 0; c4 < 16; c4++) {
        float4 a = rh[c4], bb = rw[c4];
        float q0 = qrow[c4 * 4 + 0], q1 = qrow[c4 * 4 + 1];
        float q2 = qrow[c4 * 4 + 2], q3 = qrow[c4 * 4 + 3];
        sh += q0 * a.x + q1 * a.y + q2 * a.z + q3 * a.w;
        sw += q0 * bb.x + q1 * bb.y + q2 * bb.z + q3 * bb.w;
    }
    g_bh[head * (NTOK * 64) + i * 64 + t] = sh;
    g_bw[head * (NTOK * 64) + i * 64 + t] = sw;
}

// ---------------- kernel 4: flash attention with precomputed biases ----------------
// block = (q-tile of 64 rows, head). key tile = one h2 row of 64 keys.
// Thread (tx,ty): rows r=ty*4+i, cols j=tx+16*jj. bias_w is constant across key
// tiles for a thread's (r,j) footprint -> registers. K smem tile XOR-swizzled at
// 16B granularity so strided-row float4 reads are bank-conflict-free.
__global__ __launch_bounds__(256, 2) void attn_kernel() {
    extern __shared__ float sm[];
    float* qs = sm;                // [64][64] natural
    float* ks = sm + 64 * 64;      // [64][64] swizzled; aliased by P (natural)
    float* vs = sm + 2 * 64 * 64;  // [64][64] natural
    float* ps = ks;

    int head = blockIdx.y;
    int q0 = blockIdx.x * 64;
    int tid = threadIdx.x;
    int tx = tid & 15, ty = tid >> 4;

    const float* qg = g_q + head * (NTOK * HD) + q0 * HD;
    const float* kg = g_k + head * (NTOK * HD);
    const float* vg = g_v + head * (NTOK * HD);
    const float* bhg = g_bh + head * (NTOK * 64);
    const float* bwg = g_bw + head * (NTOK * 64);

    // load q tile (contiguous)
    for (int l = tid; l < 64 * 16; l += 256)
        *(float4*)&qs[l * 4] = *(const float4*)&qg[l * 4];

    // bias_w registers (constant over key tiles)
    float bw[4][4];
#pragma unroll
    for (int i = 0; i < 4; i++)
#pragma unroll
        for (int jj = 0; jj < 4; jj++)
            bw[i][jj] = bwg[(q0 + ty * 4 + i) * 64 + tx + 16 * jj];

    float acc[4][4] = {};
    float mr[4], lr[4];
#pragma unroll
    for (int i = 0; i < 4; i++) { mr[i] = -1e30f; lr[i] = 0.f; }

    for (int kt = 0; kt < 64; kt++) {
        __syncthreads();  // prior P/V reads complete before overwrite
        // load k (swizzled) + v (natural); gmem reads fully coalesced
        for (int l = tid; l < 1024; l += 256) {
            int j = l >> 4;
            int cb = l & 15;
            float4 k4 = *(const float4*)&kg[(kt * 64 + j) * HD + cb * 4];
            *(float4*)&ks[j * 64 + ((cb ^ (j & 15)) << 2)] = k4;
            float4 v4 = *(const float4*)&vg[(kt * 64 + j) * HD + cb * 4];
            *(float4*)&vs[j * 64 + cb * 4] = v4;
        }
        __syncthreads();

        // S = (q . k) — 4x4 register tile, float4 operand loads
        float s[4][4] = {};
        for (int c = 0; c < 64; c += 4) {
            int cb = c >> 2;
            float4 q4[4];
#pragma unroll
            for (int i = 0; i < 4; i++)
                q4[i] = *(const float4*)&qs[(ty * 4 + i) * 64 + c];
#pragma unroll
            for (int jj = 0; jj < 4; jj++) {
                int j = tx + 16 * jj;
                float4 k4 = *(const float4*)&ks[j * 64 + ((cb ^ (j & 15)) << 2)];
#pragma unroll
                for (int i = 0; i < 4; i++)
                    s[i][jj] += q4[i].x * k4.x + q4[i].y * k4.y +
                                q4[i].z * k4.z + q4[i].w * k4.w;
            }
        }

        // scale + biases + online softmax (row shared by 16 lanes of same ty)
        float bh[4];
#pragma unroll
        for (int i = 0; i < 4; i++) bh[i] = bhg[(q0 + ty * 4 + i) * 64 + kt];
#pragma unroll
        for (int i = 0; i < 4; i++) {
            float mt = -1e30f;
#pragma unroll
            for (int jj = 0; jj < 4; jj++) {
                s[i][jj] = s[i][jj] * 0.125f + bh[i] + bw[i][jj];
                mt = fmaxf(mt, s[i][jj]);
            }
#pragma unroll
            for (int o = 8; o; o >>= 1)
                mt = fmaxf(mt, __shfl_xor_sync(0xffffffffu, mt, o));
            float mnew = fmaxf(mr[i], mt);
            float corr = __expf(mr[i] - mnew);
            float sum = 0.f;
#pragma unroll
            for (int jj = 0; jj < 4; jj++) {
                s[i][jj] = __expf(s[i][jj] - mnew);
                sum += s[i][jj];
            }
#pragma unroll
            for (int o = 8; o; o >>= 1)
                sum += __shfl_xor_sync(0xffffffffu, sum, o);
            lr[i] = lr[i] * corr + sum;
            mr[i] = mnew;
#pragma unroll
            for (int jj = 0; jj < 4; jj++) acc[i][jj] *= corr;
        }
        __syncthreads();  // all ks reads done before P overwrites it

        // store P (natural layout into the k buffer)
#pragma unroll
        for (int i = 0; i < 4; i++)
#pragma unroll
            for (int jj = 0; jj < 4; jj++)
                ps[(ty * 4 + i) * 64 + tx + 16 * jj] = s[i][jj];
        __syncthreads();

        // O += P @ V
        for (int k = 0; k < 64; k += 4) {
            float4 p4[4];
#pragma unroll
            for (int i = 0; i < 4; i++)
                p4[i] = *(const float4*)&ps[(ty * 4 + i) * 64 + k];
            float vvv[4][4];
#pragma unroll
            for (int kk = 0; kk < 4; kk++)
#pragma unroll
                for (int jj = 0; jj < 4; jj++)
                    vvv[kk][jj] = vs[(k + kk) * 64 + tx + 16 * jj];
#pragma unroll
            for (int i = 0; i < 4; i++) {
                float pa[4] = {p4[i].x, p4[i].y, p4[i].z, p4[i].w};
#pragma unroll
                for (int kk = 0; kk < 4; kk++)
#pragma unroll
                    for (int jj = 0; jj < 4; jj++)
                        acc[i][jj] += pa[kk] * vvv[kk][jj];
            }
        }
    }

    // write O (normalized) to [n][dim] layout for the projection GEMM
#pragma unroll
    for (int i = 0; i < 4; i++) {
        float inv = 1.f / lr[i];
#pragma unroll
        for (int jj = 0; jj < 4; jj++)
            g_o[(q0 + ty * 4 + i) * DIM + head * HD + tx + 16 * jj] =
                acc[i][jj] * inv;
    }
}

// ---------------- kernel 5: out = O @ W_proj^T + b_proj ----------------
__global__ __launch_bounds__(256) void proj_kernel(
    const float* __restrict__ W, const float* __restrict__ b,
    float* __restrict__ out) {
    __shared__ float As[16][68];
    __shared__ float Bs[16][68];
    int bm = blockIdx.y * 64;
    int bn = blockIdx.x * 64;
    int tid = threadIdx.x;
    int tx = tid & 15, ty = tid >> 4;
    int lm = tid >> 2, lk = (tid & 3) * 4;
    float acc[4][4] = {};
    for (int k0 = 0; k0 < DIM; k0 += 16) {
        float4 av = *(const float4*)&g_o[(bm + lm) * DIM + k0 + lk];
        float4 bv = *(const float4*)&W[(bn + lm) * DIM + k0 + lk];
        As[lk + 0][lm] = av.x; As[lk + 1][lm] = av.y;
        As[lk + 2][lm] = av.z; As[lk + 3][lm] = av.w;
        Bs[lk + 0][lm] = bv.x; Bs[lk + 1][lm] = bv.y;
        Bs[lk + 2][lm] = bv.z; Bs[lk + 3][lm] = bv.w;
        __syncthreads();
#pragma unroll
        for (int k = 0; k < 16; k++) {
            float4 a4 = *(const float4*)&As[k][ty * 4];
            float4 b4 = *(const float4*)&Bs[k][tx * 4];
            float a[4] = {a4.x, a4.y, a4.z, a4.w};
            float bb[4] = {b4.x, b4.y, b4.z, b4.w};
#pragma unroll
            for (int i = 0; i < 4; i++)
#pragma unroll
                for (int j = 0; j < 4; j++) acc[i][j] += a[i] * bb[j];
        }
        __syncthreads();
    }
#pragma unroll
    for (int i = 0; i < 4; i++) {
        int m = bm + ty * 4 + i;
        float4 o4;
        o4.x = acc[i][0] + b[bn + tx * 4 + 0];
        o4.y = acc[i][1] + b[bn + tx * 4 + 1];
        o4.z = acc[i][2] + b[bn + tx * 4 + 2];
        o4.w = acc[i][3] + b[bn + tx * 4 + 3];
        *(float4*)&out[m * DIM + bn + tx * 4] = o4;
    }
}

extern "C" void kernel_launch(void* const* d_in, const int* in_sizes, int n_in,
                              void* d_out, int out_size) {
    const float* x      = (const float*)d_in[0];
    const float* W_qkv  = (const float*)d_in[1];
    const float* b_qkv  = (const float*)d_in[2];
    const float* A_q    = (const float*)d_in[3];
    const float* B_q    = (const float*)d_in[4];
    const float* A_v    = (const float*)d_in[5];
    const float* B_v    = (const float*)d_in[6];
    const float* rel_h  = (const float*)d_in[7];
    const float* rel_w  = (const float*)d_in[8];
    const float* W_proj = (const float*)d_in[9];
    const float* b_proj = (const float*)d_in[10];
    float* out = (float*)d_out;

    lora_t_kernel<<<512, 256>>>(x, A_q, A_v);
    qkv_kernel<<<dim3(36, 64), 256>>>(x, W_qkv, b_qkv, B_q, B_v);
    bias_kernel<<<dim3(4096, 12), 64>>>(rel_h, rel_w);
    attn_kernel<<<dim3(64, 12), 256, 3 * 64 * 64 * sizeof(float)>>>();
    proj_kernel<<<dim3(12, 64), 256>>>(W_proj, b_proj, out);
}

// round 3
// speedup vs baseline: 1.8813x; 1.8813x over previous
#include <cuda_runtime.h>

#define NTOK 4096
#define DIM 768
#define NH 12
#define HD 64
#define RANK 4

// scratch (device globals: no allocation allowed)
__device__ float g_q[NH * NTOK * HD];
__device__ float g_k[NH * NTOK * HD];
__device__ float g_v[NH * NTOK * HD];
__device__ float g_tq[NTOK * RANK];
__device__ float g_tv[NTOK * RANK];
__device__ float g_bh[NH * NTOK * 64];
__device__ float g_bw[NH * NTOK * 64];
__device__ float g_o[NTOK * DIM];

__device__ __forceinline__ unsigned f2t(float x) {
    unsigned r;
    asm("cvt.rna.tf32.f32 %0, %1;" : "=r"(r) : "f"(x));
    return r;
}
__device__ __forceinline__ void mma8(float* c, unsigned a0, unsigned a1,
                                     unsigned a2, unsigned a3, unsigned b0,
                                     unsigned b1) {
    asm("mma.sync.aligned.m16n8k8.row.col.f32.tf32.tf32.f32 "
        "{%0,%1,%2,%3},{%4,%5,%6,%7},{%8,%9},{%0,%1,%2,%3};"
        : "+f"(c[0]), "+f"(c[1]), "+f"(c[2]), "+f"(c[3])
        : "r"(a0), "r"(a1), "r"(a2), "r"(a3), "r"(b0), "r"(b1));
}

// ---------------- kernel 1: t = x @ A^T (rank-4 LoRA down-proj) ----------------
__global__ void lora_t_kernel(const float* __restrict__ x,
                              const float* __restrict__ Aq,
                              const float* __restrict__ Av) {
    int warp = (blockIdx.x * blockDim.x + threadIdx.x) >> 5;
    int lane = threadIdx.x & 31;
    if (warp >= NTOK) return;
    const float* xr = x + warp * DIM;
    float p[8] = {0.f, 0.f, 0.f, 0.f, 0.f, 0.f, 0.f, 0.f};
    for (int i = lane; i < DIM; i += 32) {
        float xv = xr[i];
#pragma unroll
        for (int r = 0; r < RANK; r++) {
            p[r]        += xv * Aq[r * DIM + i];
            p[RANK + r] += xv * Av[r * DIM + i];
        }
    }
#pragma unroll
    for (int r = 0; r < 8; r++) {
#pragma unroll
        for (int o = 16; o; o >>= 1)
            p[r] += __shfl_xor_sync(0xffffffffu, p[r], o);
    }
    if (lane == 0) {
#pragma unroll
        for (int r = 0; r < RANK; r++) {
            g_tq[warp * RANK + r] = p[r];
            g_tv[warp * RANK + r] = p[RANK + r];
        }
    }
}

// ---------------- kernel 2: qkv = x @ W_qkv^T + b + LoRA deltas ----------------
__global__ __launch_bounds__(256) void qkv_kernel(
    const float* __restrict__ x, const float* __restrict__ W,
    const float* __restrict__ b, const float* __restrict__ Bq,
    const float* __restrict__ Bv) {
    __shared__ float As[16][68];
    __shared__ float Bs[16][68];
    int bm = blockIdx.y * 64;
    int bn = blockIdx.x * 64;
    int tid = threadIdx.x;
    int tx = tid & 15, ty = tid >> 4;
    int lm = tid >> 2, lk = (tid & 3) * 4;
    float acc[4][4] = {};
    for (int k0 = 0; k0 < DIM; k0 += 16) {
        float4 av = *(const float4*)&x[(bm + lm) * DIM + k0 + lk];
        float4 bv = *(const float4*)&W[(bn + lm) * DIM + k0 + lk];
        As[lk + 0][lm] = av.x; As[lk + 1][lm] = av.y;
        As[lk + 2][lm] = av.z; As[lk + 3][lm] = av.w;
        Bs[lk + 0][lm] = bv.x; Bs[lk + 1][lm] = bv.y;
        Bs[lk + 2][lm] = bv.z; Bs[lk + 3][lm] = bv.w;
        __syncthreads();
#pragma unroll
        for (int k = 0; k < 16; k++) {
            float4 a4 = *(const float4*)&As[k][ty * 4];
            float4 b4 = *(const float4*)&Bs[k][tx * 4];
            float a[4] = {a4.x, a4.y, a4.z, a4.w};
            float bb[4] = {b4.x, b4.y, b4.z, b4.w};
#pragma unroll
            for (int i = 0; i < 4; i++)
#pragma unroll
                for (int j = 0; j < 4; j++) acc[i][j] += a[i] * bb[j];
        }
        __syncthreads();
    }
    int col0 = bn + tx * 4;
    int which = col0 / DIM;
    int hcol0 = col0 - which * DIM;
    int head = hcol0 >> 6;
    int c0 = hcol0 & 63;
    float* dst = (which == 0) ? g_q : (which == 1 ? g_k : g_v);
#pragma unroll
    for (int i = 0; i < 4; i++) {
        int m = bm + ty * 4 + i;
        float v[4];
#pragma unroll
        for (int j = 0; j < 4; j++) {
            float val = acc[i][j] + b[col0 + j];
            if (which == 0) {
                const float* Br = &Bq[(hcol0 + j) * RANK];
                const float* tr = &g_tq[m * RANK];
                val += 0.25f * (tr[0] * Br[0] + tr[1] * Br[1] +
                                tr[2] * Br[2] + tr[3] * Br[3]);
            } else if (which == 2) {
                const float* Br = &Bv[(hcol0 + j) * RANK];
                const float* tr = &g_tv[m * RANK];
                val += 0.25f * (tr[0] * Br[0] + tr[1] * Br[1] +
                                tr[2] * Br[2] + tr[3] * Br[3]);
            }
            v[j] = val;
        }
        float4 o4 = {v[0], v[1], v[2], v[3]};
        *(float4*)&dst[head * (NTOK * HD) + m * HD + c0] = o4;
    }
}

// ---------------- kernel 3: decomposed rel-pos biases ----------------
__global__ void bias_kernel(const float* __restrict__ rel_h,
                            const float* __restrict__ rel_w) {
    int i = blockIdx.x;
    int head = blockIdx.y;
    int t = threadIdx.x;
    __shared__ float qrow[64];
    qrow[t] = g_q[head * (NTOK * HD) + i * HD + t];
    __syncthreads();
    int h1 = i >> 6, w1 = i & 63;
    const float4* rh = (const float4*)&rel_h[(h1 - t + 63) * HD];
    const float4* rw = (const float4*)&rel_w[(w1 - t + 63) * HD];
    float sh = 0.f, sw = 0.f;
#pragma unroll
    for (int c4 = 0; c4 < 16; c4++) {
        float4 a = rh[c4], bb = rw[c4];
        float q0 = qrow[c4 * 4 + 0], q1 = qrow[c4 * 4 + 1];
        float q2 = qrow[c4 * 4 + 2], q3 = qrow[c4 * 4 + 3];
        sh += q0 * a.x + q1 * a.y + q2 * a.z + q3 * a.w;
        sw += q0 * bb.x + q1 * bb.y + q2 * bb.z + q3 * bb.w;
    }
    g_bh[head * (NTOK * 64) + i * 64 + t] = sh;
    g_bw[head * (NTOK * 64) + i * 64 + t] = sw;
}

// ---------------- kernel 4: flash attention, tf32 tensor-core version ----------------
// block = 128 threads (4 warps), 64 q rows (one h1 row). Key tile = one h2 row
// (64 keys -> bias_h scalar per row per tile, bias_w loop-invariant registers).
// mma.m16n8k8.tf32: warp w owns rows w*16..w*16+15; per thread g=lane>>2, tig=lane&3.
// Smem strides (68/72/68) make all fragment-load patterns bank-conflict-free.
#define KS_ST 68
#define VS_ST 72
#define PS_ST 68
__global__ __launch_bounds__(128) void attn_kernel() {
    extern __shared__ unsigned smu[];
    unsigned* Ks = smu;                          // [64][68] tf32 bits
    unsigned* Vs = smu + 64 * KS_ST;             // [64][72]
    unsigned* Ps = smu + 64 * KS_ST + 64 * VS_ST;  // [64][68]

    int head = blockIdx.y;
    int q0 = blockIdx.x * 64;
    int tid = threadIdx.x;
    int warp = tid >> 5, lane = tid & 31;
    int g = lane >> 2, tig = lane & 3;
    int r0 = warp * 16 + g, r1 = r0 + 8;  // local q rows

    const float* qg = g_q + head * (NTOK * HD) + q0 * HD;
    const float* kg = g_k + head * (NTOK * HD);
    const float* vg = g_v + head * (NTOK * HD);
    const float* bhg = g_bh + head * (NTOK * 64);
    const float* bwg = g_bw + head * (NTOK * 64);

    // Q fragments, pre-scaled by 1/8 (exact in tf32)
    unsigned qf[8][4];
#pragma unroll
    for (int kk = 0; kk < 8; kk++) {
        qf[kk][0] = f2t(qg[r0 * 64 + kk * 8 + tig] * 0.125f);
        qf[kk][1] = f2t(qg[r1 * 64 + kk * 8 + tig] * 0.125f);
        qf[kk][2] = f2t(qg[r0 * 64 + kk * 8 + tig + 4] * 0.125f);
        qf[kk][3] = f2t(qg[r1 * 64 + kk * 8 + tig + 4] * 0.125f);
    }
    // bias_w: loop-invariant (key tile always spans w2 = 0..63)
    float bw0[16], bw1[16];
#pragma unroll
    for (int jj = 0; jj < 8; jj++) {
        float2 t0 = *(const float2*)&bwg[(q0 + r0) * 64 + jj * 8 + 2 * tig];
        float2 t1 = *(const float2*)&bwg[(q0 + r1) * 64 + jj * 8 + 2 * tig];
        bw0[2 * jj] = t0.x; bw0[2 * jj + 1] = t0.y;
        bw1[2 * jj] = t1.x; bw1[2 * jj + 1] = t1.y;
    }

    float oac[8][4] = {};
    float m0 = -1e30f, m1 = -1e30f, l0 = 0.f, l1 = 0.f;

    for (int kt = 0; kt < 64; kt++) {
        __syncthreads();  // prior-iteration K/V reads complete
        for (int l = tid; l < 1024; l += 128) {
            int j = l >> 4, cb = (l & 15) * 4;
            float4 k4 = *(const float4*)&kg[(kt * 64 + j) * 64 + cb];
            unsigned* kd = &Ks[j * KS_ST + cb];
            kd[0] = f2t(k4.x); kd[1] = f2t(k4.y);
            kd[2] = f2t(k4.z); kd[3] = f2t(k4.w);
            float4 v4 = *(const float4*)&vg[(kt * 64 + j) * 64 + cb];
            unsigned* vd = &Vs[j * VS_ST + cb];
            vd[0] = f2t(v4.x); vd[1] = f2t(v4.y);
            vd[2] = f2t(v4.z); vd[3] = f2t(v4.w);
        }
        __syncthreads();

        // S = (Q/8) . K^T
        float sac[8][4] = {};
#pragma unroll
        for (int kk = 0; kk < 8; kk++) {
#pragma unroll
            for (int jj = 0; jj < 8; jj++) {
                unsigned b0 = Ks[(jj * 8 + g) * KS_ST + kk * 8 + tig];
                unsigned b1 = Ks[(jj * 8 + g) * KS_ST + kk * 8 + tig + 4];
                mma8(sac[jj], qf[kk][0], qf[kk][1], qf[kk][2], qf[kk][3], b0, b1);
            }
        }

        // biases + online softmax
        float bh0 = __ldg(&bhg[(q0 + r0) * 64 + kt]);
        float bh1 = __ldg(&bhg[(q0 + r1) * 64 + kt]);
        float mt0 = -1e30f, mt1 = -1e30f;
#pragma unroll
        for (int jj = 0; jj < 8; jj++) {
            sac[jj][0] += bh0 + bw0[2 * jj];
            sac[jj][1] += bh0 + bw0[2 * jj + 1];
            sac[jj][2] += bh1 + bw1[2 * jj];
            sac[jj][3] += bh1 + bw1[2 * jj + 1];
            mt0 = fmaxf(mt0, fmaxf(sac[jj][0], sac[jj][1]));
            mt1 = fmaxf(mt1, fmaxf(sac[jj][2], sac[jj][3]));
        }
#pragma unroll
        for (int o = 1; o < 4; o <<= 1) {
            mt0 = fmaxf(mt0, __shfl_xor_sync(0xffffffffu, mt0, o));
            mt1 = fmaxf(mt1, __shfl_xor_sync(0xffffffffu, mt1, o));
        }
        float mn0 = fmaxf(m0, mt0), mn1 = fmaxf(m1, mt1);
        float c0 = __expf(m0 - mn0), c1 = __expf(m1 - mn1);
        float s0 = 0.f, s1 = 0.f;
#pragma unroll
        for (int jj = 0; jj < 8; jj++) {
            sac[jj][0] = __expf(sac[jj][0] - mn0);
            sac[jj][1] = __expf(sac[jj][1] - mn0);
            sac[jj][2] = __expf(sac[jj][2] - mn1);
            sac[jj][3] = __expf(sac[jj][3] - mn1);
            s0 += sac[jj][0] + sac[jj][1];
            s1 += sac[jj][2] + sac[jj][3];
        }
#pragma unroll
        for (int o = 1; o < 4; o <<= 1) {
            s0 += __shfl_xor_sync(0xffffffffu, s0, o);
            s1 += __shfl_xor_sync(0xffffffffu, s1, o);
        }
        l0 = l0 * c0 + s0; l1 = l1 * c1 + s1;
        m0 = mn0; m1 = mn1;
#pragma unroll
        for (int jj = 0; jj < 8; jj++) {
            oac[jj][0] *= c0; oac[jj][1] *= c0;
            oac[jj][2] *= c1; oac[jj][3] *= c1;
        }

        // store P (tf32 bits) — each warp writes only its own 16 rows
#pragma unroll
        for (int jj = 0; jj < 8; jj++) {
            Ps[r0 * PS_ST + jj * 8 + 2 * tig]     = f2t(sac[jj][0]);
            Ps[r0 * PS_ST + jj * 8 + 2 * tig + 1] = f2t(sac[jj][1]);
            Ps[r1 * PS_ST + jj * 8 + 2 * tig]     = f2t(sac[jj][2]);
            Ps[r1 * PS_ST + jj * 8 + 2 * tig + 1] = f2t(sac[jj][3]);
        }
        __syncwarp();  // warp-local: A-frags below read only this warp's rows

        // O += P @ V
#pragma unroll
        for (int kk = 0; kk < 8; kk++) {
            unsigned a0 = Ps[r0 * PS_ST + kk * 8 + tig];
            unsigned a1 = Ps[r1 * PS_ST + kk * 8 + tig];
            unsigned a2 = Ps[r0 * PS_ST + kk * 8 + tig + 4];
            unsigned a3 = Ps[r1 * PS_ST + kk * 8 + tig + 4];
#pragma unroll
            for (int jj = 0; jj < 8; jj++) {
                unsigned b0 = Vs[(kk * 8 + tig) * VS_ST + jj * 8 + g];
                unsigned b1 = Vs[(kk * 8 + tig + 4) * VS_ST + jj * 8 + g];
                mma8(oac[jj], a0, a1, a2, a3, b0, b1);
            }
        }
    }

    float inv0 = 1.f / l0, inv1 = 1.f / l1;
#pragma unroll
    for (int jj = 0; jj < 8; jj++) {
        int c = head * 64 + jj * 8 + 2 * tig;
        float2 o0 = {oac[jj][0] * inv0, oac[jj][1] * inv0};
        float2 o1 = {oac[jj][2] * inv1, oac[jj][3] * inv1};
        *(float2*)&g_o[(q0 + r0) * DIM + c] = o0;
        *(float2*)&g_o[(q0 + r1) * DIM + c] = o1;
    }
}

// ---------------- kernel 5: out = O @ W_proj^T + b_proj ----------------
__global__ __launch_bounds__(256) void proj_kernel(
    const float* __restrict__ W, const float* __restrict__ b,
    float* __restrict__ out) {
    __shared__ float As[16][68];
    __shared__ float Bs[16][68];
    int bm = blockIdx.y * 64;
    int bn = blockIdx.x * 64;
    int tid = threadIdx.x;
    int tx = tid & 15, ty = tid >> 4;
    int lm = tid >> 2, lk = (tid & 3) * 4;
    float acc[4][4] = {};
    for (int k0 = 0; k0 < DIM; k0 += 16) {
        float4 av = *(const float4*)&g_o[(bm + lm) * DIM + k0 + lk];
        float4 bv = *(const float4*)&W[(bn + lm) * DIM + k0 + lk];
        As[lk + 0][lm] = av.x; As[lk + 1][lm] = av.y;
        As[lk + 2][lm] = av.z; As[lk + 3][lm] = av.w;
        Bs[lk + 0][lm] = bv.x; Bs[lk + 1][lm] = bv.y;
        Bs[lk + 2][lm] = bv.z; Bs[lk + 3][lm] = bv.w;
        __syncthreads();
#pragma unroll
        for (int k = 0; k < 16; k++) {
            float4 a4 = *(const float4*)&As[k][ty * 4];
            float4 b4 = *(const float4*)&Bs[k][tx * 4];
            float a[4] = {a4.x, a4.y, a4.z, a4.w};
            float bb[4] = {b4.x, b4.y, b4.z, b4.w};
#pragma unroll
            for (int i = 0; i < 4; i++)
#pragma unroll
                for (int j = 0; j < 4; j++) acc[i][j] += a[i] * bb[j];
        }
        __syncthreads();
    }
#pragma unroll
    for (int i = 0; i < 4; i++) {
        int m = bm + ty * 4 + i;
        float4 o4;
        o4.x = acc[i][0] + b[bn + tx * 4 + 0];
        o4.y = acc[i][1] + b[bn + tx * 4 + 1];
        o4.z = acc[i][2] + b[bn + tx * 4 + 2];
        o4.w = acc[i][3] + b[bn + tx * 4 + 3];
        *(float4*)&out[m * DIM + bn + tx * 4] = o4;
    }
}

extern "C" void kernel_launch(void* const* d_in, const int* in_sizes, int n_in,
                              void* d_out, int out_size) {
    const float* x      = (const float*)d_in[0];
    const float* W_qkv  = (const float*)d_in[1];
    const float* b_qkv  = (const float*)d_in[2];
    const float* A_q    = (const float*)d_in[3];
    const float* B_q    = (const float*)d_in[4];
    const float* A_v    = (const float*)d_in[5];
    const float* B_v    = (const float*)d_in[6];
    const float* rel_h  = (const float*)d_in[7];
    const float* rel_w  = (const float*)d_in[8];
    const float* W_proj = (const float*)d_in[9];
    const float* b_proj = (const float*)d_in[10];
    float* out = (float*)d_out;

    static int smem_set = 0;
    int attn_smem = (64 * KS_ST + 64 * VS_ST + 64 * PS_ST) * 4;  // 53248 B
    if (!smem_set) {
        cudaFuncSetAttribute(attn_kernel,
                             cudaFuncAttributeMaxDynamicSharedMemorySize,
                             attn_smem);
        smem_set = 1;
    }

    lora_t_kernel<<<512, 256>>>(x, A_q, A_v);
    qkv_kernel<<<dim3(36, 64), 256>>>(x, W_qkv, b_qkv, B_q, B_v);
    bias_kernel<<<dim3(4096, 12), 64>>>(rel_h, rel_w);
    attn_kernel<<<dim3(64, 12), 128, attn_smem>>>();
    proj_kernel<<<dim3(12, 64), 256>>>(W_proj, b_proj, out);
}

// round 6
// speedup vs baseline: 3.5267x; 1.8746x over previous
#include <cuda_runtime.h>

#define NTOK 4096
#define DIM 768
#define NH 12
#define HD 64
#define RANK 4

// scratch (device globals: no allocation allowed)
__device__ float g_q[NH * NTOK * HD];
__device__ float g_k[NH * NTOK * HD];
__device__ float g_v[NH * NTOK * HD];
__device__ float g_tq[NTOK * RANK];
__device__ float g_tv[NTOK * RANK];
__device__ float g_bh[NH * NTOK * 64];
__device__ float g_bw[NH * NTOK * 64];
__device__ float g_o[NTOK * DIM];

__device__ __forceinline__ unsigned f2t(float x) {
    unsigned r;
    asm("cvt.rna.tf32.f32 %0, %1;" : "=r"(r) : "f"(x));
    return r;
}
__device__ __forceinline__ void mma8(float* c, unsigned a0, unsigned a1,
                                     unsigned a2, unsigned a3, unsigned b0,
                                     unsigned b1) {
    asm("mma.sync.aligned.m16n8k8.row.col.f32.tf32.tf32.f32 "
        "{%0,%1,%2,%3},{%4,%5,%6,%7},{%8,%9},{%0,%1,%2,%3};"
        : "+f"(c[0]), "+f"(c[1]), "+f"(c[2]), "+f"(c[3])
        : "r"(a0), "r"(a1), "r"(a2), "r"(a3), "r"(b0), "r"(b1));
}

// ---------------- kernel 1: t = x @ A^T (rank-4 LoRA down-proj) ----------------
__global__ void lora_t_kernel(const float* __restrict__ x,
                              const float* __restrict__ Aq,
                              const float* __restrict__ Av) {
    int warp = (blockIdx.x * blockDim.x + threadIdx.x) >> 5;
    int lane = threadIdx.x & 31;
    if (warp >= NTOK) return;
    const float* xr = x + warp * DIM;
    float p[8] = {0.f, 0.f, 0.f, 0.f, 0.f, 0.f, 0.f, 0.f};
    for (int i = lane; i < DIM; i += 32) {
        float xv = xr[i];
#pragma unroll
        for (int r = 0; r < RANK; r++) {
            p[r]        += xv * Aq[r * DIM + i];
            p[RANK + r] += xv * Av[r * DIM + i];
        }
    }
#pragma unroll
    for (int r = 0; r < 8; r++) {
#pragma unroll
        for (int o = 16; o; o >>= 1)
            p[r] += __shfl_xor_sync(0xffffffffu, p[r], o);
    }
    if (lane == 0) {
#pragma unroll
        for (int r = 0; r < RANK; r++) {
            g_tq[warp * RANK + r] = p[r];
            g_tv[warp * RANK + r] = p[RANK + r];
        }
    }
}

// ---------------- tf32 GEMM mainloop (shared by qkv/proj) ----------------
// 128x128 tile, BK=32, 256 threads = 8 warps, warp tile 64x32 (m16n8k8 grid 4x4).
// A[M,K] row-major, B[N,K] row-major (NT). smem stride 36 -> all fragment
// loads (banks 4*row + k) are conflict-free.
#define GST 36
#define GEMM_MAINLOOP(APTR, BPTR)                                              \
    __shared__ unsigned As[128 * GST];                                         \
    __shared__ unsigned Bs[128 * GST];                                         \
    int tid = threadIdx.x;                                                     \
    int warp = tid >> 5, lane = tid & 31;                                      \
    int g = lane >> 2, tig = lane & 3;                                         \
    int wm = warp & 1, wn = warp >> 1;                                         \
    int bm = blockIdx.y * 128, bn = blockIdx.x * 128;                          \
    int lrow = tid >> 1, lcol = (tid & 1) * 16;                                \
    float acc[4][4][4] = {};                                                   \
    for (int k0 = 0; k0 < DIM; k0 += 32) {                                     \
        _Pragma("unroll") for (int q = 0; q < 4; q++) {                        \
            float4 a4 = *(const float4*)&(APTR)[(bm + lrow) * DIM + k0 +       \
                                               lcol + q * 4];                  \
            unsigned* ad = &As[lrow * GST + lcol + q * 4];                     \
            ad[0] = f2t(a4.x); ad[1] = f2t(a4.y);                              \
            ad[2] = f2t(a4.z); ad[3] = f2t(a4.w);                              \
            float4 b4 = *(const float4*)&(BPTR)[(bn + lrow) * DIM + k0 +       \
                                               lcol + q * 4];                  \
            unsigned* bd = &Bs[lrow * GST + lcol + q * 4];                     \
            bd[0] = f2t(b4.x); bd[1] = f2t(b4.y);                              \
            bd[2] = f2t(b4.z); bd[3] = f2t(b4.w);                              \
        }                                                                      \
        __syncthreads();                                                       \
        _Pragma("unroll") for (int k8 = 0; k8 < 4; k8++) {                     \
            unsigned af[4][4], bf[4][2];                                       \
            _Pragma("unroll") for (int mt = 0; mt < 4; mt++) {                 \
                int r = (wm * 64 + mt * 16 + g) * GST + k8 * 8 + tig;          \
                af[mt][0] = As[r];            af[mt][1] = As[r + 8 * GST];     \
                af[mt][2] = As[r + 4];        af[mt][3] = As[r + 8 * GST + 4]; \
            }                                                                  \
            _Pragma("unroll") for (int nt = 0; nt < 4; nt++) {                 \
                int r = (wn * 32 + nt * 8 + g) * GST + k8 * 8 + tig;           \
                bf[nt][0] = Bs[r]; bf[nt][1] = Bs[r + 4];                      \
            }                                                                  \
            _Pragma("unroll") for (int mt = 0; mt < 4; mt++)                   \
                _Pragma("unroll") for (int nt = 0; nt < 4; nt++)               \
                    mma8(acc[mt][nt], af[mt][0], af[mt][1], af[mt][2],         \
                         af[mt][3], bf[nt][0], bf[nt][1]);                     \
        }                                                                      \
        __syncthreads();                                                       \
    }

// ---------------- kernel 2: qkv = x @ W_qkv^T + b + LoRA deltas ----------------
__global__ __launch_bounds__(256) void qkv_tc_kernel(
    const float* __restrict__ x, const float* __restrict__ W,
    const float* __restrict__ b, const float* __restrict__ Bq,
    const float* __restrict__ Bv) {
    GEMM_MAINLOOP(x, W)
    // epilogue: 128-col tile lies within one of q/k/v (768 % 128 == 0)
    int which = bn / DIM;
    int hb = bn - which * DIM;
    float* dst = (which == 0) ? g_q : (which == 1 ? g_k : g_v);
#pragma unroll
    for (int mt = 0; mt < 4; mt++) {
#pragma unroll
        for (int h = 0; h < 2; h++) {
            int m = bm + wm * 64 + mt * 16 + g + 8 * h;
            float4 t4 = {0.f, 0.f, 0.f, 0.f};
            if (which == 0) t4 = *(const float4*)&g_tq[m * RANK];
            if (which == 2) t4 = *(const float4*)&g_tv[m * RANK];
#pragma unroll
            for (int nt = 0; nt < 4; nt++) {
                int cb = wn * 32 + nt * 8 + 2 * tig;
                int hcol = hb + cb;
                int head = hcol >> 6, c = hcol & 63;
                float v0 = acc[mt][nt][2 * h + 0] + b[bn + cb];
                float v1 = acc[mt][nt][2 * h + 1] + b[bn + cb + 1];
                if (which != 1) {
                    const float* Bp = ((which == 0) ? Bq : Bv) + hcol * RANK;
                    v0 += 0.25f * (t4.x * Bp[0] + t4.y * Bp[1] +
                                   t4.z * Bp[2] + t4.w * Bp[3]);
                    v1 += 0.25f * (t4.x * Bp[4] + t4.y * Bp[5] +
                                   t4.z * Bp[6] + t4.w * Bp[7]);
                }
                float2 o2 = {v0, v1};
                *(float2*)&dst[head * (NTOK * HD) + m * HD + c] = o2;
            }
        }
    }
}

// ---------------- kernel 5: out = O @ W_proj^T + b_proj ----------------
__global__ __launch_bounds__(256) void proj_tc_kernel(
    const float* __restrict__ W, const float* __restrict__ bp,
    float* __restrict__ out) {
    GEMM_MAINLOOP(g_o, W)
#pragma unroll
    for (int mt = 0; mt < 4; mt++) {
#pragma unroll
        for (int h = 0; h < 2; h++) {
            int m = bm + wm * 64 + mt * 16 + g + 8 * h;
#pragma unroll
            for (int nt = 0; nt < 4; nt++) {
                int n = bn + wn * 32 + nt * 8 + 2 * tig;
                float2 o2 = {acc[mt][nt][2 * h + 0] + bp[n],
                             acc[mt][nt][2 * h + 1] + bp[n + 1]};
                *(float2*)&out[m * DIM + n] = o2;
            }
        }
    }
}

// ---------------- kernel 3: decomposed rel-pos biases as 64x64x64 GEMM blocks --
// mode 0 (bias_h): block (h1, head): out[w1][h2] = q[head, h1*64+w1, :] . rel_h[h1-h2+63, :]
// mode 1 (bias_w): block (w1, head): out[h1][w2] = q[head, h1*64+w1, :] . rel_w[w1-w2+63, :]
// NOTE: destination selected in DEVICE code (g_bh/g_bw are __device__ symbols;
// passing them as host-side kernel args was the R4/R5 correctness bug).
__global__ __launch_bounds__(256) void bias2_kernel(
    const float* __restrict__ rel, int mode) {
    float* outg = mode ? g_bw : g_bh;
    __shared__ float Qs[64][68];  // [c][t]
    __shared__ float Rs[64][68];  // [c][j]
    int f = blockIdx.x;     // h1 (mode 0) or w1 (mode 1)
    int head = blockIdx.y;
    int tid = threadIdx.x;
    int row = tid >> 2, cb = (tid & 3) * 16;
    int gi = (mode == 0) ? (f * 64 + row) : (row * 64 + f);
    const float* qp = &g_q[head * (NTOK * HD) + gi * HD + cb];
    const float* rp = &rel[(f + 63 - row) * HD + cb];
#pragma unroll
    for (int q4 = 0; q4 < 4; q4++) {
        float4 qv = *(const float4*)&qp[q4 * 4];
        float4 rv = *(const float4*)&rp[q4 * 4];
        int c = cb + q4 * 4;
        Qs[c + 0][row] = qv.x; Qs[c + 1][row] = qv.y;
        Qs[c + 2][row] = qv.z; Qs[c + 3][row] = qv.w;
        Rs[c + 0][row] = rv.x; Rs[c + 1][row] = rv.y;
        Rs[c + 2][row] = rv.z; Rs[c + 3][row] = rv.w;
    }
    __syncthreads();
    int tx = tid & 15, ty = tid >> 4;
    float s[4][4] = {};
#pragma unroll
    for (int c = 0; c < 64; c++) {
        float4 a4 = *(const float4*)&Qs[c][ty * 4];
        float4 b4 = *(const float4*)&Rs[c][tx * 4];
        float a[4] = {a4.x, a4.y, a4.z, a4.w};
        float bb[4] = {b4.x, b4.y, b4.z, b4.w};
#pragma unroll
        for (int i = 0; i < 4; i++)
#pragma unroll
            for (int j = 0; j < 4; j++) s[i][j] += a[i] * bb[j];
    }
#pragma unroll
    for (int i = 0; i < 4; i++) {
        int t = ty * 4 + i;
        int ig = (mode == 0) ? (f * 64 + t) : (t * 64 + f);
        float4 o4 = {s[i][0], s[i][1], s[i][2], s[i][3]};
        *(float4*)&outg[head * (NTOK * 64) + ig * 64 + tx * 4] = o4;
    }
}

// ---------------- kernel 4: flash attention, tf32 tensor-core version ----------------
#define KS_ST 68
#define VS_ST 72
#define PS_ST 68
__global__ __launch_bounds__(128) void attn_kernel() {
    extern __shared__ unsigned smu[];
    unsigned* Ks = smu;                            // [64][68] tf32 bits
    unsigned* Vs = smu + 64 * KS_ST;               // [64][72]
    unsigned* Ps = smu + 64 * KS_ST + 64 * VS_ST;  // [64][68]

    int head = blockIdx.y;
    int q0 = blockIdx.x * 64;
    int tid = threadIdx.x;
    int warp = tid >> 5, lane = tid & 31;
    int g = lane >> 2, tig = lane & 3;
    int r0 = warp * 16 + g, r1 = r0 + 8;

    const float* qg = g_q + head * (NTOK * HD) + q0 * HD;
    const float* kg = g_k + head * (NTOK * HD);
    const float* vg = g_v + head * (NTOK * HD);
    const float* bhg = g_bh + head * (NTOK * 64);
    const float* bwg = g_bw + head * (NTOK * 64);

    unsigned qf[8][4];
#pragma unroll
    for (int kk = 0; kk < 8; kk++) {
        qf[kk][0] = f2t(qg[r0 * 64 + kk * 8 + tig] * 0.125f);
        qf[kk][1] = f2t(qg[r1 * 64 + kk * 8 + tig] * 0.125f);
        qf[kk][2] = f2t(qg[r0 * 64 + kk * 8 + tig + 4] * 0.125f);
        qf[kk][3] = f2t(qg[r1 * 64 + kk * 8 + tig + 4] * 0.125f);
    }
    float bw0[16], bw1[16];
#pragma unroll
    for (int jj = 0; jj < 8; jj++) {
        float2 t0 = *(const float2*)&bwg[(q0 + r0) * 64 + jj * 8 + 2 * tig];
        float2 t1 = *(const float2*)&bwg[(q0 + r1) * 64 + jj * 8 + 2 * tig];
        bw0[2 * jj] = t0.x; bw0[2 * jj + 1] = t0.y;
        bw1[2 * jj] = t1.x; bw1[2 * jj + 1] = t1.y;
    }

    float oac[8][4] = {};
    float m0 = -1e30f, m1 = -1e30f, l0 = 0.f, l1 = 0.f;

    for (int kt = 0; kt < 64; kt++) {
        __syncthreads();
        for (int l = tid; l < 1024; l += 128) {
            int j = l >> 4, cb = (l & 15) * 4;
            float4 k4 = *(const float4*)&kg[(kt * 64 + j) * 64 + cb];
            unsigned* kd = &Ks[j * KS_ST + cb];
            kd[0] = f2t(k4.x); kd[1] = f2t(k4.y);
            kd[2] = f2t(k4.z); kd[3] = f2t(k4.w);
            float4 v4 = *(const float4*)&vg[(kt * 64 + j) * 64 + cb];
            unsigned* vd = &Vs[j * VS_ST + cb];
            vd[0] = f2t(v4.x); vd[1] = f2t(v4.y);
            vd[2] = f2t(v4.z); vd[3] = f2t(v4.w);
        }
        __syncthreads();

        float sac[8][4] = {};
#pragma unroll
        for (int kk = 0; kk < 8; kk++) {
#pragma unroll
            for (int jj = 0; jj < 8; jj++) {
                unsigned b0 = Ks[(jj * 8 + g) * KS_ST + kk * 8 + tig];
                unsigned b1 = Ks[(jj * 8 + g) * KS_ST + kk * 8 + tig + 4];
                mma8(sac[jj], qf[kk][0], qf[kk][1], qf[kk][2], qf[kk][3], b0, b1);
            }
        }

        float bh0 = __ldg(&bhg[(q0 + r0) * 64 + kt]);
        float bh1 = __ldg(&bhg[(q0 + r1) * 64 + kt]);
        float mt0 = -1e30f, mt1 = -1e30f;
#pragma unroll
        for (int jj = 0; jj < 8; jj++) {
            sac[jj][0] += bh0 + bw0[2 * jj];
            sac[jj][1] += bh0 + bw0[2 * jj + 1];
            sac[jj][2] += bh1 + bw1[2 * jj];
            sac[jj][3] += bh1 + bw1[2 * jj + 1];
            mt0 = fmaxf(mt0, fmaxf(sac[jj][0], sac[jj][1]));
            mt1 = fmaxf(mt1, fmaxf(sac[jj][2], sac[jj][3]));
        }
#pragma unroll
        for (int o = 1; o < 4; o <<= 1) {
            mt0 = fmaxf(mt0, __shfl_xor_sync(0xffffffffu, mt0, o));
            mt1 = fmaxf(mt1, __shfl_xor_sync(0xffffffffu, mt1, o));
        }
        float mn0 = fmaxf(m0, mt0), mn1 = fmaxf(m1, mt1);
        float c0 = __expf(m0 - mn0), c1 = __expf(m1 - mn1);
        float s0 = 0.f, s1 = 0.f;
#pragma unroll
        for (int jj = 0; jj < 8; jj++) {
            sac[jj][0] = __expf(sac[jj][0] - mn0);
            sac[jj][1] = __expf(sac[jj][1] - mn0);
            sac[jj][2] = __expf(sac[jj][2] - mn1);
            sac[jj][3] = __expf(sac[jj][3] - mn1);
            s0 += sac[jj][0] + sac[jj][1];
            s1 += sac[jj][2] + sac[jj][3];
        }
#pragma unroll
        for (int o = 1; o < 4; o <<= 1) {
            s0 += __shfl_xor_sync(0xffffffffu, s0, o);
            s1 += __shfl_xor_sync(0xffffffffu, s1, o);
        }
        l0 = l0 * c0 + s0; l1 = l1 * c1 + s1;
        m0 = mn0; m1 = mn1;
#pragma unroll
        for (int jj = 0; jj < 8; jj++) {
            oac[jj][0] *= c0; oac[jj][1] *= c0;
            oac[jj][2] *= c1; oac[jj][3] *= c1;
        }

#pragma unroll
        for (int jj = 0; jj < 8; jj++) {
            Ps[r0 * PS_ST + jj * 8 + 2 * tig]     = f2t(sac[jj][0]);
            Ps[r0 * PS_ST + jj * 8 + 2 * tig + 1] = f2t(sac[jj][1]);
            Ps[r1 * PS_ST + jj * 8 + 2 * tig]     = f2t(sac[jj][2]);
            Ps[r1 * PS_ST + jj * 8 + 2 * tig + 1] = f2t(sac[jj][3]);
        }
        __syncwarp();

#pragma unroll
        for (int kk = 0; kk < 8; kk++) {
            unsigned a0 = Ps[r0 * PS_ST + kk * 8 + tig];
            unsigned a1 = Ps[r1 * PS_ST + kk * 8 + tig];
            unsigned a2 = Ps[r0 * PS_ST + kk * 8 + tig + 4];
            unsigned a3 = Ps[r1 * PS_ST + kk * 8 + tig + 4];
#pragma unroll
            for (int jj = 0; jj < 8; jj++) {
                unsigned b0 = Vs[(kk * 8 + tig) * VS_ST + jj * 8 + g];
                unsigned b1 = Vs[(kk * 8 + tig + 4) * VS_ST + jj * 8 + g];
                mma8(oac[jj], a0, a1, a2, a3, b0, b1);
            }
        }
    }

    float inv0 = 1.f / l0, inv1 = 1.f / l1;
#pragma unroll
    for (int jj = 0; jj < 8; jj++) {
        int c = head * 64 + jj * 8 + 2 * tig;
        float2 o0 = {oac[jj][0] * inv0, oac[jj][1] * inv0};
        float2 o1 = {oac[jj][2] * inv1, oac[jj][3] * inv1};
        *(float2*)&g_o[(q0 + r0) * DIM + c] = o0;
        *(float2*)&g_o[(q0 + r1) * DIM + c] = o1;
    }
}

extern "C" void kernel_launch(void* const* d_in, const int* in_sizes, int n_in,
                              void* d_out, int out_size) {
    const float* x      = (const float*)d_in[0];
    const float* W_qkv  = (const float*)d_in[1];
    const float* b_qkv  = (const float*)d_in[2];
    const float* A_q    = (const float*)d_in[3];
    const float* B_q    = (const float*)d_in[4];
    const float* A_v    = (const float*)d_in[5];
    const float* B_v    = (const float*)d_in[6];
    const float* rel_h  = (const float*)d_in[7];
    const float* rel_w  = (const float*)d_in[8];
    const float* W_proj = (const float*)d_in[9];
    const float* b_proj = (const float*)d_in[10];
    float* out = (float*)d_out;

    static int smem_set = 0;
    int attn_smem = (64 * KS_ST + 64 * VS_ST + 64 * PS_ST) * 4;  // 53248 B
    if (!smem_set) {
        cudaFuncSetAttribute(attn_kernel,
                             cudaFuncAttributeMaxDynamicSharedMemorySize,
                             attn_smem);
        smem_set = 1;
    }

    lora_t_kernel<<<512, 256>>>(x, A_q, A_v);
    qkv_tc_kernel<<<dim3(18, 32), 256>>>(x, W_qkv, b_qkv, B_q, B_v);
    bias2_kernel<<<dim3(64, 12), 256>>>(rel_h, 0);
    bias2_kernel<<<dim3(64, 12), 256>>>(rel_w, 1);
    attn_kernel<<<dim3(64, 12), 128, attn_smem>>>();
    proj_tc_kernel<<<dim3(6, 32), 256>>>(W_proj, b_proj, out);
}